// round 14
// baseline (speedup 1.0000x reference)
#include <cuda_runtime.h>
#include <cstdint>
#include <math.h>

#define DINL __device__ __forceinline__

// ---------------- problem constants ----------------
constexpr int NG   = 100000;     // graph nodes
constexpr int NC   = 10;         // candidates
constexpr int NTOT = NG + NC;    // 100010
constexpr int FIN  = 128;
constexpr int T    = 10;         // types
constexpr int EMAX = 6400000;

// ---------------- scratch (__device__ globals; no allocation allowed) ----------------
__device__ __align__(128) float g_hA[NTOT * 32];
__device__ __align__(128) float g_hB[NTOT * 32];
__device__ __align__(128) float g_t [NTOT * 32];
__device__ __align__(128) float g_agg[NTOT * 32];
__device__ float g_deg [NTOT];
__device__ float g_dinv[NTOT];
__device__ int   g_src [EMAX];
__device__ int   g_dst [EMAX];
__device__ float g_coef[EMAX];
__device__ __align__(128) float g_zs[NTOT * T];
__device__ __align__(128) float g_ze[NTOT * T];
__device__ float g_part[256 * T];
__device__ float g_M[T];
__device__ float g_S[T];
__device__ int   g_cnt[T];
__device__ int   g_sn [NTOT];    // start_node as int
__device__ int   g_is64;         // edge_index dtype flag

// ---------------- TF32 rounding (match XLA/cuBLAS default f32 matmul) -------
DINL float tf32r(float x) {
    uint32_t r;
    asm("cvt.rna.tf32.f32 %0, %1;" : "=r"(r) : "f"(x));
    return __uint_as_float(r);
}

// ---------------- threefry2x32 (exact JAX, partitionable) ----------------
struct KP { uint32_t a, b; };

__host__ __device__ constexpr uint32_t rotl32(uint32_t x, int r) {
    return (x << r) | (x >> (32 - r));
}

__host__ __device__ constexpr KP tf2x32(uint32_t k0, uint32_t k1, uint32_t c0, uint32_t c1) {
    uint32_t ks0 = k0, ks1 = k1, ks2 = k0 ^ k1 ^ 0x1BD11BDAu;
    uint32_t x0 = c0 + ks0, x1 = c1 + ks1;
    const int r0[4] = {13, 15, 26, 6};
    const int r1[4] = {17, 29, 16, 24};
    for (int i = 0; i < 4; i++) { x0 += x1; x1 = rotl32(x1, r0[i]); x1 ^= x0; }
    x0 += ks1; x1 += ks2 + 1u;
    for (int i = 0; i < 4; i++) { x0 += x1; x1 = rotl32(x1, r1[i]); x1 ^= x0; }
    x0 += ks2; x1 += ks0 + 2u;
    for (int i = 0; i < 4; i++) { x0 += x1; x1 = rotl32(x1, r0[i]); x1 ^= x0; }
    x0 += ks0; x1 += ks1 + 3u;
    for (int i = 0; i < 4; i++) { x0 += x1; x1 = rotl32(x1, r1[i]); x1 ^= x0; }
    x0 += ks1; x1 += ks2 + 4u;
    for (int i = 0; i < 4; i++) { x0 += x1; x1 = rotl32(x1, r0[i]); x1 ^= x0; }
    x0 += ks2; x1 += ks0 + 5u;
    return {x0, x1};
}

// jax.random.key(42) -> (0, 42); partitionable split:
// subkey_i = (bits1, bits2) of threefry2x32(key, hi=0, lo=i)
constexpr KP SK0 = tf2x32(0u, 42u, 0u, 0u);   // k1
constexpr KP SK1 = tf2x32(0u, 42u, 0u, 1u);   // k2
constexpr uint32_t K1A = SK0.a, K1B = SK0.b;
constexpr uint32_t K2A = SK1.a, K2B = SK1.b;

constexpr float JAX_TINY = 1.17549435e-38f;

// partitionable random_bits(key,32,shape)[i] = bits1 ^ bits2 of tf(key, hi(i), lo(i)).
// gumbel = -log(-log(uniform(tiny,1))). Inner math in double: within <=1 ulp of
// libdevice float chain, independent of --use_fast_math.
DINL float jax_gumbel(uint32_t k0, uint32_t k1, uint32_t idx) {
    KP o = tf2x32(k0, k1, 0u, idx);
    uint32_t bits = o.a ^ o.b;
    float f = __uint_as_float((bits >> 9) | 0x3f800000u) - 1.0f;   // [0,1)
    float u = fmaxf(JAX_TINY, f + JAX_TINY);                        // uniform(tiny,1)
    double l1 = -log((double)u);
    return (float)(-log(l1));
}

// ---------------- kernels ----------------
// Detect int64 vs int32 index dtype from candidate_idx (= arange(100000,100010)).
__global__ void k_detect(const int* __restrict__ cidx) {
    g_is64 = (cidx[1] == 0) ? 1 : 0;
}

__global__ void k_init(int n) {
    int i = blockIdx.x * blockDim.x + threadIdx.x;
    if (i < n) g_deg[i] = 1.0f;           // +1 self-loop term of degree
    if (i < T) g_cnt[i] = 0;
}

__global__ void k_degree(const void* __restrict__ eiv, int e) {
    int i = blockIdx.x * blockDim.x + threadIdx.x;
    if (i >= e) return;
    int d;
    if (g_is64) d = (int)((const long long*)eiv)[(size_t)e + i];
    else        d = ((const int*)eiv)[e + i];
    atomicAdd(&g_deg[d], 1.0f);
}

__global__ void k_dinv(int n) {
    int i = blockIdx.x * blockDim.x + threadIdx.x;
    if (i < n) g_dinv[i] = rsqrtf(g_deg[i]);   // match XLA lax.rsqrt (libdevice)
}

__global__ void k_prep(const void* __restrict__ eiv, int e) {
    int i = blockIdx.x * blockDim.x + threadIdx.x;
    if (i >= e) return;
    int s, d;
    if (g_is64) {
        s = (int)((const long long*)eiv)[i];
        d = (int)((const long long*)eiv)[(size_t)e + i];
    } else {
        s = ((const int*)eiv)[i];
        d = ((const int*)eiv)[e + i];
    }
    g_src[i] = s; g_dst[i] = d;
    g_coef[i] = g_dinv[s] * g_dinv[d];
}

// Zero g_agg referencing the device symbol DIRECTLY (never pass a __device__
// global as a host-side kernel arg: on GB300 ATS the host-shadow address is
// silently writable and the device buffer is never touched).
__global__ void k_zeroagg(int count) {
    int i = blockIdx.x * blockDim.x + threadIdx.x;
    if (i < count) g_agg[i] = 0.0f;
}

// t = hin @ W  with TF32 operand rounding (matches XLA default GPU matmul).
// SRCSEL: 0 = concat(x,cand) from params, 1 = g_hA, 2 = g_hB
template <int Fin, int Fout, int SRCSEL>
__global__ void k_gemm(const float* __restrict__ x, const float* __restrict__ cand,
                       const float* __restrict__ W, int n) {
    __shared__ float sW[Fin * Fout];
    for (int i = threadIdx.x; i < Fin * Fout; i += blockDim.x) sW[i] = tf32r(W[i]);
    __syncthreads();
    int row = blockIdx.x * blockDim.x + threadIdx.x;
    if (row >= n) return;
    const float* src;
    if (SRCSEL == 0) src = (row >= NG) ? (cand + (size_t)(row - NG) * Fin)
                                       : (x + (size_t)row * Fin);
    else if (SRCSEL == 1) src = g_hA + (size_t)row * Fin;
    else                  src = g_hB + (size_t)row * Fin;
    float acc[Fout];
#pragma unroll
    for (int f = 0; f < Fout; f++) acc[f] = 0.0f;
    for (int k = 0; k < Fin; k++) {
        float xv = tf32r(src[k]);
#pragma unroll
        for (int f = 0; f < Fout; f++) acc[f] = fmaf(xv, sW[k * Fout + f], acc[f]);
    }
#pragma unroll
    for (int f = 0; f < Fout; f++) g_t[(size_t)row * Fout + f] = acc[f];
}

// agg[dst] += t[src] * coef   (float4 vector atomics, sm_90+)
template <int Fout>
__global__ void k_scatter(int e) {
    constexpr int PER = Fout / 4;
    long long gid = (long long)blockIdx.x * blockDim.x + threadIdx.x;
    if (gid >= (long long)e * PER) return;
    int ed = (int)(gid / PER);
    int c  = (int)(gid - (long long)ed * PER);
    int s = g_src[ed], d = g_dst[ed];
    float cf = g_coef[ed];
    float4 v = *(const float4*)(g_t + (size_t)s * Fout + c * 4);
    v.x *= cf; v.y *= cf; v.z *= cf; v.w *= cf;
    atomicAdd((float4*)(g_agg + (size_t)d * Fout + c * 4), v);
}

// hout = (agg + t*dinv^2) + b   (DSTSEL: 1 = g_hA, 2 = g_hB)
template <int Fout, int DSTSEL>
__global__ void k_fin(const float* __restrict__ b, int n) {
    int i = blockIdx.x * blockDim.x + threadIdx.x;
    if (i >= n * Fout) return;
    int row = i / Fout, f = i - row * Fout;
    float dv = g_dinv[row];
    float* dst = (DSTSEL == 1) ? g_hA : g_hB;
    dst[i] = (g_agg[i] + g_t[i] * (dv * dv)) + b[f];
}

// z = relu6(h@W1 + b1) @ W2 + b2 ; both matmuls TF32-rounded.
// (h = g_hA [n,32]; ZSEL: 0 -> g_zs, 1 -> g_ze)
template <int H, int ZSEL>
__global__ void k_head(const float* __restrict__ W1, const float* __restrict__ b1,
                       const float* __restrict__ W2, const float* __restrict__ b2, int n) {
    __shared__ float sW1[32 * H], sB1[H], sW2[H * T], sB2[T];
    for (int i = threadIdx.x; i < 32 * H; i += blockDim.x) sW1[i] = tf32r(W1[i]);
    for (int i = threadIdx.x; i < H * T;  i += blockDim.x) sW2[i] = tf32r(W2[i]);
    if (threadIdx.x < H) sB1[threadIdx.x] = b1[threadIdx.x];
    if (threadIdx.x < T) sB2[threadIdx.x] = b2[threadIdx.x];
    __syncthreads();
    int row = blockIdx.x * blockDim.x + threadIdx.x;
    if (row >= n) return;
    float hv[32];
#pragma unroll
    for (int k = 0; k < 32; k++) hv[k] = tf32r(g_hA[(size_t)row * 32 + k]);
    float s1[H];
#pragma unroll
    for (int j = 0; j < H; j++) {
        float a = 0.0f;
#pragma unroll
        for (int k = 0; k < 32; k++) a = fmaf(hv[k], sW1[k * H + j], a);
        a += sB1[j];
        s1[j] = tf32r(fminf(fmaxf(a, 0.0f), 6.0f));   // relu6, then TF32 for 2nd gemm
    }
    float* z = (ZSEL == 0) ? g_zs : g_ze;
#pragma unroll
    for (int t = 0; t < T; t++) {
        float a = 0.0f;
#pragma unroll
        for (int j = 0; j < H; j++) a = fmaf(s1[j], sW2[j * T + t], a);
        z[(size_t)row * T + t] = a + sB2[t];
    }
}

// column max over axis 0, partial per block (grid must be 256 blocks)
template <int ZSEL>
__global__ void k_colmax(int n) {
    const float* z = (ZSEL == 0) ? g_zs : g_ze;
    float m[T];
#pragma unroll
    for (int t = 0; t < T; t++) m[t] = -3.402823466e38f;
    for (int row = blockIdx.x * blockDim.x + threadIdx.x; row < n;
         row += gridDim.x * blockDim.x)
#pragma unroll
        for (int t = 0; t < T; t++) m[t] = fmaxf(m[t], z[(size_t)row * T + t]);
    __shared__ float sm[256 * T];
#pragma unroll
    for (int t = 0; t < T; t++) sm[t * 256 + threadIdx.x] = m[t];
    __syncthreads();
    for (int s = 128; s > 0; s >>= 1) {
        if (threadIdx.x < s)
#pragma unroll
            for (int t = 0; t < T; t++)
                sm[t * 256 + threadIdx.x] =
                    fmaxf(sm[t * 256 + threadIdx.x], sm[t * 256 + threadIdx.x + s]);
        __syncthreads();
    }
    if (threadIdx.x == 0)
#pragma unroll
        for (int t = 0; t < T; t++) g_part[blockIdx.x * T + t] = sm[t * 256];
}

__global__ void k_redmax() {
    int t = threadIdx.x;
    if (t < T) {
        float m = -3.402823466e38f;
        for (int b = 0; b < 256; b++) m = fmaxf(m, g_part[b * T + t]);
        g_M[t] = m;
    }
}

// precise exp via double (flag-independent, <=1 ulp of libdevice expf)
DINL float pexp(float x) { return (float)exp((double)x); }

template <int ZSEL>
__global__ void k_colsum(int n) {
    const float* z = (ZSEL == 0) ? g_zs : g_ze;
    float M[T], s[T];
#pragma unroll
    for (int t = 0; t < T; t++) { M[t] = g_M[t]; s[t] = 0.0f; }
    for (int row = blockIdx.x * blockDim.x + threadIdx.x; row < n;
         row += gridDim.x * blockDim.x)
#pragma unroll
        for (int t = 0; t < T; t++) s[t] += pexp(z[(size_t)row * T + t] - M[t]);
    __shared__ float sm[256 * T];
#pragma unroll
    for (int t = 0; t < T; t++) sm[t * 256 + threadIdx.x] = s[t];
    __syncthreads();
    for (int st = 128; st > 0; st >>= 1) {
        if (threadIdx.x < st)
#pragma unroll
            for (int t = 0; t < T; t++)
                sm[t * 256 + threadIdx.x] += sm[t * 256 + threadIdx.x + st];
        __syncthreads();
    }
    if (threadIdx.x == 0)
#pragma unroll
        for (int t = 0; t < T; t++) g_part[blockIdx.x * T + t] = sm[t * 256];
}

// addCand: add sum_c cnt[c]*exp(ze[c,t]-M[t]) for the duplicated rows of `combined`
__global__ void k_redsum(int addCand) {
    int t = threadIdx.x;
    if (t < T) {
        float s = 0.0f;
        for (int b = 0; b < 256; b++) s += g_part[b * T + t];
        if (addCand)
            for (int c = 0; c < T; c++)
                s += (float)g_cnt[c] * pexp(g_ze[c * T + t] - g_M[t]);
        g_S[t] = s;
    }
}

// p and log(p) in double, rounded once (flag-independent)
DINL void prob_logp(float zmM, float S, float& pf, float& lpf) {
    double pd = exp((double)zmM) / (double)S;
    pf = (float)pd;
    lpf = (float)log(pd);
}

// start: probs, candidate mask, categorical(k1), histogram of start_node
__global__ void k_start(float* __restrict__ out_node, float* __restrict__ out_probs,
                        int n) {
    __shared__ int hist[T];
    if (threadIdx.x < T) hist[threadIdx.x] = 0;
    __syncthreads();
    float M[T], S[T];
#pragma unroll
    for (int t = 0; t < T; t++) { M[t] = g_M[t]; S[t] = g_S[t]; }
    const float lp10 = (float)log(1e-10);
    for (int row = blockIdx.x * blockDim.x + threadIdx.x; row < n;
         row += gridDim.x * blockDim.x) {
        float best = -3.402823466e38f; int bi = 0;
        uint32_t base = (uint32_t)row * T;
#pragma unroll
        for (int t = 0; t < T; t++) {
            float pf, lpf;
            prob_logp(g_zs[(size_t)row * T + t] - M[t], S[t], pf, lpf);
            if (row >= NG) { pf = 1e-10f; lpf = lp10; }   // candidate mask
            out_probs[(size_t)row * T + t] = pf;
            float v = jax_gumbel(K1A, K1B, base + t) + lpf;
            if (v > best) { best = v; bi = t; }
        }
        out_node[row] = (float)bi;
        g_sn[row] = bi;
        atomicAdd(&hist[bi], 1);
    }
    __syncthreads();
    if (threadIdx.x < T) atomicAdd(&g_cnt[threadIdx.x], hist[threadIdx.x]);
}

// end rows [0,n): softmax probs; rows whose index appears in start_node values
// (subset of 0..9) are zeroed -> 1e-10; sample with k2.
__global__ void k_end1(float* __restrict__ out_node, float* __restrict__ out_probs,
                       int n) {
    float M[T], S[T]; int zr[T];
#pragma unroll
    for (int t = 0; t < T; t++) { M[t] = g_M[t]; S[t] = g_S[t]; zr[t] = (g_cnt[t] > 0); }
    const float lp10 = (float)log(1e-10);
    for (int row = blockIdx.x * blockDim.x + threadIdx.x; row < n;
         row += gridDim.x * blockDim.x) {
        float best = -3.402823466e38f; int bi = 0;
        uint32_t base = (uint32_t)row * T;
        bool zero_row = (row < T) && zr[row];
#pragma unroll
        for (int t = 0; t < T; t++) {
            float pf, lpf;
            prob_logp(g_ze[(size_t)row * T + t] - M[t], S[t], pf, lpf);
            if (zero_row) { pf = 1e-10f; lpf = lp10; }
            out_probs[(size_t)row * T + t] = pf;
            float v = jax_gumbel(K2A, K2B, base + t) + lpf;
            if (v > best) { best = v; bi = t; }
        }
        out_node[row] = (float)bi;
    }
}

// end rows [n,2n): row n+i duplicates ze row start_node[i] (values 0..9).
// These rows are NEVER zeroed (set(0) only hits row indices < 10).
__global__ void k_end2(float* __restrict__ out_node, float* __restrict__ out_probs,
                       int n) {
    __shared__ float sp[T * T];    // prob of dup rows: sp[c*T+t]
    __shared__ float sl[T * T];    // log prob
    if (threadIdx.x < T * T) {
        int c = threadIdx.x / T, t = threadIdx.x - c * T;
        float pf, lpf;
        prob_logp(g_ze[c * T + t] - g_M[t], g_S[t], pf, lpf);
        sp[threadIdx.x] = pf;
        sl[threadIdx.x] = lpf;
    }
    __syncthreads();
    for (int i = blockIdx.x * blockDim.x + threadIdx.x; i < n;
         i += gridDim.x * blockDim.x) {
        int row = n + i;
        int sn = g_sn[i];
        float best = -3.402823466e38f; int bi = 0;
        uint32_t base = (uint32_t)row * T;
#pragma unroll
        for (int t = 0; t < T; t++) {
            out_probs[(size_t)row * T + t] = sp[sn * T + t];
            float v = jax_gumbel(K2A, K2B, base + t) + sl[sn * T + t];
            if (v > best) { best = v; bi = t; }
        }
        out_node[row] = (float)bi;
    }
}

// ---------------- launch ----------------
extern "C" void kernel_launch(void* const* d_in, const int* in_sizes, int n_in,
                              void* d_out, int out_size) {
    const float* x    = (const float*)d_in[0];
    const float* cand = (const float*)d_in[1];
    const void*  ei   = d_in[2];
    const int*   cidx = (const int*)d_in[3];
    const float *W1 = (const float*)d_in[4],  *b1 = (const float*)d_in[5];
    const float *W2 = (const float*)d_in[6],  *b2 = (const float*)d_in[7];
    const float *W3 = (const float*)d_in[8],  *b3 = (const float*)d_in[9];
    const float *Ws1 = (const float*)d_in[10], *bs1 = (const float*)d_in[11];
    const float *Ws2 = (const float*)d_in[12], *bs2 = (const float*)d_in[13];
    const float *We1 = (const float*)d_in[14], *be1 = (const float*)d_in[15];
    const float *We2 = (const float*)d_in[16], *be2 = (const float*)d_in[17];

    int n = in_sizes[0] / FIN + in_sizes[1] / FIN;   // 100010
    int E = in_sizes[2] / 2;

    float* out   = (float*)d_out;
    float* o_sn  = out;                          // start_node [n]
    float* o_en  = out + n;                      // end_node [2n]
    float* o_sp  = out + 3 * (size_t)n;          // start_probs [n,10]
    float* o_ep  = out + 3 * (size_t)n + (size_t)T * n;  // end_probs [2n,10]

    const int TB = 256;
    auto gb = [](long long w, int tb) { return (unsigned)((w + tb - 1) / tb); };

    k_detect<<<1, 1>>>(cidx);
    k_init<<<gb(n, TB), TB>>>(n);
    k_degree<<<gb(E, TB), TB>>>(ei, E);
    k_dinv<<<gb(n, TB), TB>>>(n);
    k_prep<<<gb(E, TB), TB>>>(ei, E);

    // layer 1: concat(x,cand) -> hA  (128 -> 16)
    k_gemm<128, 16, 0><<<gb(n, 128), 128>>>(x, cand, W1, n);
    k_zeroagg<<<gb((long long)n * 16, TB), TB>>>(n * 16);
    k_scatter<16><<<gb((long long)E * 4, TB), TB>>>(E);
    k_fin<16, 1><<<gb((long long)n * 16, TB), TB>>>(b1, n);

    // layer 2: hA -> hB  (16 -> 24)
    k_gemm<16, 24, 1><<<gb(n, 128), 128>>>(nullptr, nullptr, W2, n);
    k_zeroagg<<<gb((long long)n * 24, TB), TB>>>(n * 24);
    k_scatter<24><<<gb((long long)E * 6, TB), TB>>>(E);
    k_fin<24, 2><<<gb((long long)n * 24, TB), TB>>>(b2, n);

    // layer 3: hB -> hA  (24 -> 32)
    k_gemm<24, 32, 2><<<gb(n, 128), 128>>>(nullptr, nullptr, W3, n);
    k_zeroagg<<<gb((long long)n * 32, TB), TB>>>(n * 32);
    k_scatter<32><<<gb((long long)E * 8, TB), TB>>>(E);
    k_fin<32, 1><<<gb((long long)n * 32, TB), TB>>>(b3, n);

    // start head + column softmax stats + sampling
    k_head<16, 0><<<gb(n, 128), 128>>>(Ws1, bs1, Ws2, bs2, n);
    k_colmax<0><<<256, 256>>>(n);
    k_redmax<<<1, 32>>>();
    k_colsum<0><<<256, 256>>>(n);
    k_redsum<<<1, 32>>>(0);
    k_start<<<256, 256>>>(o_sn, o_sp, n);

    // end head: only n distinct rows (second half of `combined` duplicates rows 0..9)
    k_head<24, 1><<<gb(n, 128), 128>>>(We1, be1, We2, be2, n);
    k_colmax<1><<<256, 256>>>(n);
    k_redmax<<<1, 32>>>();
    k_colsum<1><<<256, 256>>>(n);
    k_redsum<<<1, 32>>>(1);           // adds duplicated-row terms via cnt[]
    k_end1<<<256, 256>>>(o_en, o_ep, n);
    k_end2<<<256, 256>>>(o_en, o_ep, n);
}

// round 15
// speedup vs baseline: 1.2578x; 1.2578x over previous
#include <cuda_runtime.h>
#include <cstdint>
#include <math.h>

#define DINL __device__ __forceinline__

// ---------------- problem constants ----------------
constexpr int NG   = 100000;     // graph nodes
constexpr int NC   = 10;         // candidates
constexpr int NTOT = NG + NC;    // 100010
constexpr int FIN  = 128;
constexpr int T    = 10;         // types
constexpr int EMAX = 6400000;
constexpr int SC_B = (NTOT + 255) / 256;   // 391 scan blocks

// ---------------- scratch (__device__ globals; no allocation) ----------------
__device__ __align__(128) float g_hA[NTOT * 32];
__device__ __align__(128) float g_hB[NTOT * 32];
__device__ __align__(128) float g_t [NTOT * 32];   // t' = (h@W)*dinv[row]
__device__ float g_dinv[NTOT];
__device__ int   g_icnt[NTOT];    // in-degree (without self loop)
__device__ int   g_off [NTOT];    // CSR row offsets (by dst)
__device__ int   g_cur [NTOT];    // fill cursors
__device__ int   g_csrc[EMAX];    // CSR column = src node
__device__ int   g_bsum[512];
__device__ int   g_bpre[512];
__device__ __align__(128) float g_zs[NTOT * T];
__device__ __align__(128) float g_ze[NTOT * T];
__device__ float g_part[256 * T];
__device__ float g_M[T];
__device__ float g_S[T];
__device__ int   g_cnt[T];
__device__ int   g_sn [NTOT];
__device__ int   g_is64;

// ---------------- TF32 rounding (match XLA default f32 matmul) -------
DINL float tf32r(float x) {
    uint32_t r;
    asm("cvt.rna.tf32.f32 %0, %1;" : "=r"(r) : "f"(x));
    return __uint_as_float(r);
}

// ---------------- threefry2x32 (exact JAX, partitionable) ----------------
struct KP { uint32_t a, b; };

__host__ __device__ constexpr uint32_t rotl32(uint32_t x, int r) {
    return (x << r) | (x >> (32 - r));
}

__host__ __device__ constexpr KP tf2x32(uint32_t k0, uint32_t k1, uint32_t c0, uint32_t c1) {
    uint32_t ks0 = k0, ks1 = k1, ks2 = k0 ^ k1 ^ 0x1BD11BDAu;
    uint32_t x0 = c0 + ks0, x1 = c1 + ks1;
    const int r0[4] = {13, 15, 26, 6};
    const int r1[4] = {17, 29, 16, 24};
    for (int i = 0; i < 4; i++) { x0 += x1; x1 = rotl32(x1, r0[i]); x1 ^= x0; }
    x0 += ks1; x1 += ks2 + 1u;
    for (int i = 0; i < 4; i++) { x0 += x1; x1 = rotl32(x1, r1[i]); x1 ^= x0; }
    x0 += ks2; x1 += ks0 + 2u;
    for (int i = 0; i < 4; i++) { x0 += x1; x1 = rotl32(x1, r0[i]); x1 ^= x0; }
    x0 += ks0; x1 += ks1 + 3u;
    for (int i = 0; i < 4; i++) { x0 += x1; x1 = rotl32(x1, r1[i]); x1 ^= x0; }
    x0 += ks1; x1 += ks2 + 4u;
    for (int i = 0; i < 4; i++) { x0 += x1; x1 = rotl32(x1, r0[i]); x1 ^= x0; }
    x0 += ks2; x1 += ks0 + 5u;
    return {x0, x1};
}

constexpr KP SK0 = tf2x32(0u, 42u, 0u, 0u);   // k1
constexpr KP SK1 = tf2x32(0u, 42u, 0u, 1u);   // k2
constexpr uint32_t K1A = SK0.a, K1B = SK0.b;
constexpr uint32_t K2A = SK1.a, K2B = SK1.b;

constexpr float JAX_TINY = 1.17549435e-38f;

DINL float jax_gumbel(uint32_t k0, uint32_t k1, uint32_t idx) {
    KP o = tf2x32(k0, k1, 0u, idx);
    uint32_t bits = o.a ^ o.b;
    float f = __uint_as_float((bits >> 9) | 0x3f800000u) - 1.0f;   // [0,1)
    float u = fmaxf(JAX_TINY, f + JAX_TINY);
    double l1 = -log((double)u);
    return (float)(-log(l1));
}

// ---------------- edge-index access (int32/int64 agnostic) ----------------
DINL int ei_at(const void* eiv, size_t idx) {
    if (g_is64) return (int)((const long long*)eiv)[idx];
    return ((const int*)eiv)[idx];
}

// ---------------- CSR build ----------------
__global__ void k_detect(const int* __restrict__ cidx) {
    g_is64 = (cidx[1] == 0) ? 1 : 0;
}

__global__ void k_zcnt(int n) {
    int i = blockIdx.x * blockDim.x + threadIdx.x;
    if (i < n) g_icnt[i] = 0;
    if (i < T) g_cnt[i] = 0;
}

__global__ void k_hist(const void* __restrict__ eiv, int e) {
    int i = blockIdx.x * blockDim.x + threadIdx.x;
    if (i >= e) return;
    atomicAdd(&g_icnt[ei_at(eiv, (size_t)e + i)], 1);
}

__global__ void k_scansum(int n) {               // grid SC_B, block 256
    __shared__ int sm[256];
    int i = blockIdx.x * 256 + threadIdx.x;
    sm[threadIdx.x] = (i < n) ? g_icnt[i] : 0;
    __syncthreads();
    for (int s = 128; s > 0; s >>= 1) {
        if (threadIdx.x < s) sm[threadIdx.x] += sm[threadIdx.x + s];
        __syncthreads();
    }
    if (threadIdx.x == 0) g_bsum[blockIdx.x] = sm[0];
}

__global__ void k_scanblk(int nb) {
    if (threadIdx.x == 0) {
        int acc = 0;
        for (int b = 0; b < nb; b++) { g_bpre[b] = acc; acc += g_bsum[b]; }
    }
}

__global__ void k_scanout(int n) {               // grid SC_B, block 256
    __shared__ int sm[256];
    int i = blockIdx.x * 256 + threadIdx.x;
    int v = (i < n) ? g_icnt[i] : 0;
    sm[threadIdx.x] = v;
    __syncthreads();
    for (int s = 1; s < 256; s <<= 1) {
        int t = (threadIdx.x >= s) ? sm[threadIdx.x - s] : 0;
        __syncthreads();
        sm[threadIdx.x] += t;
        __syncthreads();
    }
    if (i < n) {
        int off = g_bpre[blockIdx.x] + sm[threadIdx.x] - v;   // exclusive
        g_off[i] = off;
        g_cur[i] = off;
    }
}

__global__ void k_dinv(int n) {
    int i = blockIdx.x * blockDim.x + threadIdx.x;
    if (i < n) g_dinv[i] = rsqrtf((float)g_icnt[i] + 1.0f);
}

__global__ void k_fill(const void* __restrict__ eiv, int e) {
    int i = blockIdx.x * blockDim.x + threadIdx.x;
    if (i >= e) return;
    int s = ei_at(eiv, i);
    int d = ei_at(eiv, (size_t)e + i);
    int pos = atomicAdd(&g_cur[d], 1);
    g_csrc[pos] = s;
}

// ---------------- GCN layers ----------------
// t' = (hin @ W) * dinv[row]   (float4 loads; TF32 operand rounding)
// SRCSEL: 0 = concat(x,cand), 1 = g_hA, 2 = g_hB
template <int Fin, int Fout, int SRCSEL>
__global__ void k_gemm(const float* __restrict__ x, const float* __restrict__ cand,
                       const float* __restrict__ W, int n) {
    __shared__ float sW[Fin * Fout];
    for (int i = threadIdx.x; i < Fin * Fout; i += blockDim.x) sW[i] = tf32r(W[i]);
    __syncthreads();
    int row = blockIdx.x * blockDim.x + threadIdx.x;
    if (row >= n) return;
    const float* src;
    if (SRCSEL == 0) src = (row >= NG) ? (cand + (size_t)(row - NG) * Fin)
                                       : (x + (size_t)row * Fin);
    else if (SRCSEL == 1) src = g_hA + (size_t)row * Fin;
    else                  src = g_hB + (size_t)row * Fin;
    float acc[Fout];
#pragma unroll
    for (int f = 0; f < Fout; f++) acc[f] = 0.0f;
    const float4* src4 = (const float4*)src;
#pragma unroll
    for (int k4 = 0; k4 < Fin / 4; k4++) {
        float4 xv = src4[k4];
        float xs[4] = {tf32r(xv.x), tf32r(xv.y), tf32r(xv.z), tf32r(xv.w)};
#pragma unroll
        for (int q = 0; q < 4; q++) {
            int k = k4 * 4 + q;
#pragma unroll
            for (int f = 0; f < Fout; f++) acc[f] = fmaf(xs[q], sW[k * Fout + f], acc[f]);
        }
    }
    float dv = g_dinv[row];
#pragma unroll
    for (int f = 0; f < Fout; f++) g_t[(size_t)row * Fout + f] = acc[f] * dv;
}

// out[d] = dinv[d] * (sum_{s in N(d)} t'[s] + t'[d]) + b   (pull; no atomics)
template <int F, int DSTSEL>
__global__ void k_gather(const float* __restrict__ b, int n) {
    constexpr int PER = F / 4;
    int tid = blockIdx.x * blockDim.x + threadIdx.x;
    if (tid >= n * PER) return;
    int d = tid / PER, c = tid - d * PER;
    int beg = g_off[d];
    int end = beg + g_icnt[d];
    float4 acc = make_float4(0.f, 0.f, 0.f, 0.f);
    for (int j = beg; j < end; j++) {
        int s = __ldg(&g_csrc[j]);
        float4 v = *(const float4*)(g_t + (size_t)s * F + c * 4);
        acc.x += v.x; acc.y += v.y; acc.z += v.z; acc.w += v.w;
    }
    float4 tv = *(const float4*)(g_t + (size_t)d * F + c * 4);
    float dv = g_dinv[d];
    float* dst = (DSTSEL == 1) ? g_hA : g_hB;
    float4 o;
    o.x = (acc.x + tv.x) * dv + b[c * 4 + 0];
    o.y = (acc.y + tv.y) * dv + b[c * 4 + 1];
    o.z = (acc.z + tv.z) * dv + b[c * 4 + 2];
    o.w = (acc.w + tv.w) * dv + b[c * 4 + 3];
    *(float4*)(dst + (size_t)d * F + c * 4) = o;
}

// ---------------- heads + softmax + sampling ----------------
template <int H, int ZSEL>
__global__ void k_head(const float* __restrict__ W1, const float* __restrict__ b1,
                       const float* __restrict__ W2, const float* __restrict__ b2, int n) {
    __shared__ float sW1[32 * H], sB1[H], sW2[H * T], sB2[T];
    for (int i = threadIdx.x; i < 32 * H; i += blockDim.x) sW1[i] = tf32r(W1[i]);
    for (int i = threadIdx.x; i < H * T;  i += blockDim.x) sW2[i] = tf32r(W2[i]);
    if (threadIdx.x < H) sB1[threadIdx.x] = b1[threadIdx.x];
    if (threadIdx.x < T) sB2[threadIdx.x] = b2[threadIdx.x];
    __syncthreads();
    int row = blockIdx.x * blockDim.x + threadIdx.x;
    if (row >= n) return;
    float hv[32];
    const float4* h4 = (const float4*)(g_hA + (size_t)row * 32);
#pragma unroll
    for (int k4 = 0; k4 < 8; k4++) {
        float4 v = h4[k4];
        hv[k4 * 4 + 0] = tf32r(v.x); hv[k4 * 4 + 1] = tf32r(v.y);
        hv[k4 * 4 + 2] = tf32r(v.z); hv[k4 * 4 + 3] = tf32r(v.w);
    }
    float s1[H];
#pragma unroll
    for (int j = 0; j < H; j++) {
        float a = 0.0f;
#pragma unroll
        for (int k = 0; k < 32; k++) a = fmaf(hv[k], sW1[k * H + j], a);
        a += sB1[j];
        s1[j] = tf32r(fminf(fmaxf(a, 0.0f), 6.0f));
    }
    float* z = (ZSEL == 0) ? g_zs : g_ze;
#pragma unroll
    for (int t = 0; t < T; t++) {
        float a = 0.0f;
#pragma unroll
        for (int j = 0; j < H; j++) a = fmaf(s1[j], sW2[j * T + t], a);
        z[(size_t)row * T + t] = a + sB2[t];
    }
}

template <int ZSEL>
__global__ void k_colmax(int n) {
    const float* z = (ZSEL == 0) ? g_zs : g_ze;
    float m[T];
#pragma unroll
    for (int t = 0; t < T; t++) m[t] = -3.402823466e38f;
    for (int row = blockIdx.x * blockDim.x + threadIdx.x; row < n;
         row += gridDim.x * blockDim.x)
#pragma unroll
        for (int t = 0; t < T; t++) m[t] = fmaxf(m[t], z[(size_t)row * T + t]);
    __shared__ float sm[256 * T];
#pragma unroll
    for (int t = 0; t < T; t++) sm[t * 256 + threadIdx.x] = m[t];
    __syncthreads();
    for (int s = 128; s > 0; s >>= 1) {
        if (threadIdx.x < s)
#pragma unroll
            for (int t = 0; t < T; t++)
                sm[t * 256 + threadIdx.x] =
                    fmaxf(sm[t * 256 + threadIdx.x], sm[t * 256 + threadIdx.x + s]);
        __syncthreads();
    }
    if (threadIdx.x == 0)
#pragma unroll
        for (int t = 0; t < T; t++) g_part[blockIdx.x * T + t] = sm[t * 256];
}

__global__ void k_redmax() {
    int t = threadIdx.x;
    if (t < T) {
        float m = -3.402823466e38f;
        for (int b = 0; b < 256; b++) m = fmaxf(m, g_part[b * T + t]);
        g_M[t] = m;
    }
}

DINL float pexp(float x) { return (float)exp((double)x); }

template <int ZSEL>
__global__ void k_colsum(int n) {
    const float* z = (ZSEL == 0) ? g_zs : g_ze;
    float M[T], s[T];
#pragma unroll
    for (int t = 0; t < T; t++) { M[t] = g_M[t]; s[t] = 0.0f; }
    for (int row = blockIdx.x * blockDim.x + threadIdx.x; row < n;
         row += gridDim.x * blockDim.x)
#pragma unroll
        for (int t = 0; t < T; t++) s[t] += pexp(z[(size_t)row * T + t] - M[t]);
    __shared__ float sm[256 * T];
#pragma unroll
    for (int t = 0; t < T; t++) sm[t * 256 + threadIdx.x] = s[t];
    __syncthreads();
    for (int st = 128; st > 0; st >>= 1) {
        if (threadIdx.x < st)
#pragma unroll
            for (int t = 0; t < T; t++)
                sm[t * 256 + threadIdx.x] += sm[t * 256 + threadIdx.x + st];
        __syncthreads();
    }
    if (threadIdx.x == 0)
#pragma unroll
        for (int t = 0; t < T; t++) g_part[blockIdx.x * T + t] = sm[t * 256];
}

__global__ void k_redsum(int addCand) {
    int t = threadIdx.x;
    if (t < T) {
        float s = 0.0f;
        for (int b = 0; b < 256; b++) s += g_part[b * T + t];
        if (addCand)
            for (int c = 0; c < T; c++)
                s += (float)g_cnt[c] * pexp(g_ze[c * T + t] - g_M[t]);
        g_S[t] = s;
    }
}

DINL void prob_logp(float zmM, float S, float& pf, float& lpf) {
    double pd = exp((double)zmM) / (double)S;
    pf = (float)pd;
    lpf = (float)log(pd);
}

__global__ void k_start(float* __restrict__ out_node, float* __restrict__ out_probs,
                        int n) {
    __shared__ int hist[T];
    if (threadIdx.x < T) hist[threadIdx.x] = 0;
    __syncthreads();
    float M[T], S[T];
#pragma unroll
    for (int t = 0; t < T; t++) { M[t] = g_M[t]; S[t] = g_S[t]; }
    const float lp10 = (float)log(1e-10);
    for (int row = blockIdx.x * blockDim.x + threadIdx.x; row < n;
         row += gridDim.x * blockDim.x) {
        float best = -3.402823466e38f; int bi = 0;
        uint32_t base = (uint32_t)row * T;
#pragma unroll
        for (int t = 0; t < T; t++) {
            float pf, lpf;
            prob_logp(g_zs[(size_t)row * T + t] - M[t], S[t], pf, lpf);
            if (row >= NG) { pf = 1e-10f; lpf = lp10; }
            out_probs[(size_t)row * T + t] = pf;
            float v = jax_gumbel(K1A, K1B, base + t) + lpf;
            if (v > best) { best = v; bi = t; }
        }
        out_node[row] = (float)bi;
        g_sn[row] = bi;
        atomicAdd(&hist[bi], 1);
    }
    __syncthreads();
    if (threadIdx.x < T) atomicAdd(&g_cnt[threadIdx.x], hist[threadIdx.x]);
}

__global__ void k_end1(float* __restrict__ out_node, float* __restrict__ out_probs,
                       int n) {
    float M[T], S[T]; int zr[T];
#pragma unroll
    for (int t = 0; t < T; t++) { M[t] = g_M[t]; S[t] = g_S[t]; zr[t] = (g_cnt[t] > 0); }
    const float lp10 = (float)log(1e-10);
    for (int row = blockIdx.x * blockDim.x + threadIdx.x; row < n;
         row += gridDim.x * blockDim.x) {
        float best = -3.402823466e38f; int bi = 0;
        uint32_t base = (uint32_t)row * T;
        bool zero_row = (row < T) && zr[row];
#pragma unroll
        for (int t = 0; t < T; t++) {
            float pf, lpf;
            prob_logp(g_ze[(size_t)row * T + t] - M[t], S[t], pf, lpf);
            if (zero_row) { pf = 1e-10f; lpf = lp10; }
            out_probs[(size_t)row * T + t] = pf;
            float v = jax_gumbel(K2A, K2B, base + t) + lpf;
            if (v > best) { best = v; bi = t; }
        }
        out_node[row] = (float)bi;
    }
}

__global__ void k_end2(float* __restrict__ out_node, float* __restrict__ out_probs,
                       int n) {
    __shared__ float sp[T * T];
    __shared__ float sl[T * T];
    if (threadIdx.x < T * T) {
        int c = threadIdx.x / T, t = threadIdx.x - c * T;
        float pf, lpf;
        prob_logp(g_ze[c * T + t] - g_M[t], g_S[t], pf, lpf);
        sp[threadIdx.x] = pf;
        sl[threadIdx.x] = lpf;
    }
    __syncthreads();
    for (int i = blockIdx.x * blockDim.x + threadIdx.x; i < n;
         i += gridDim.x * blockDim.x) {
        int row = n + i;
        int sn = g_sn[i];
        float best = -3.402823466e38f; int bi = 0;
        uint32_t base = (uint32_t)row * T;
#pragma unroll
        for (int t = 0; t < T; t++) {
            out_probs[(size_t)row * T + t] = sp[sn * T + t];
            float v = jax_gumbel(K2A, K2B, base + t) + sl[sn * T + t];
            if (v > best) { best = v; bi = t; }
        }
        out_node[row] = (float)bi;
    }
}

// ---------------- launch ----------------
extern "C" void kernel_launch(void* const* d_in, const int* in_sizes, int n_in,
                              void* d_out, int out_size) {
    const float* x    = (const float*)d_in[0];
    const float* cand = (const float*)d_in[1];
    const void*  ei   = d_in[2];
    const int*   cidx = (const int*)d_in[3];
    const float *W1 = (const float*)d_in[4],  *b1 = (const float*)d_in[5];
    const float *W2 = (const float*)d_in[6],  *b2 = (const float*)d_in[7];
    const float *W3 = (const float*)d_in[8],  *b3 = (const float*)d_in[9];
    const float *Ws1 = (const float*)d_in[10], *bs1 = (const float*)d_in[11];
    const float *Ws2 = (const float*)d_in[12], *bs2 = (const float*)d_in[13];
    const float *We1 = (const float*)d_in[14], *be1 = (const float*)d_in[15];
    const float *We2 = (const float*)d_in[16], *be2 = (const float*)d_in[17];

    int n = in_sizes[0] / FIN + in_sizes[1] / FIN;   // 100010
    int E = in_sizes[2] / 2;

    float* out   = (float*)d_out;
    float* o_sn  = out;
    float* o_en  = out + n;
    float* o_sp  = out + 3 * (size_t)n;
    float* o_ep  = out + 3 * (size_t)n + (size_t)T * n;

    const int TB = 256;
    auto gb = [](long long w, int tb) { return (unsigned)((w + tb - 1) / tb); };

    // --- CSR build ---
    k_detect<<<1, 1>>>(cidx);
    k_zcnt<<<gb(n, TB), TB>>>(n);
    k_hist<<<gb(E, TB), TB>>>(ei, E);
    k_scansum<<<SC_B, 256>>>(n);
    k_scanblk<<<1, 32>>>(SC_B);
    k_scanout<<<SC_B, 256>>>(n);
    k_dinv<<<gb(n, TB), TB>>>(n);
    k_fill<<<gb(E, TB), TB>>>(ei, E);

    // --- layer 1: concat(x,cand) -> hA  (128 -> 16) ---
    k_gemm<128, 16, 0><<<gb(n, 128), 128>>>(x, cand, W1, n);
    k_gather<16, 1><<<gb((long long)n * 4, TB), TB>>>(b1, n);

    // --- layer 2: hA -> hB  (16 -> 24) ---
    k_gemm<16, 24, 1><<<gb(n, 128), 128>>>(nullptr, nullptr, W2, n);
    k_gather<24, 2><<<gb((long long)n * 6, TB), TB>>>(b2, n);

    // --- layer 3: hB -> hA  (24 -> 32) ---
    k_gemm<24, 32, 2><<<gb(n, 128), 128>>>(nullptr, nullptr, W3, n);
    k_gather<32, 1><<<gb((long long)n * 8, TB), TB>>>(b3, n);

    // --- start head ---
    k_head<16, 0><<<gb(n, 128), 128>>>(Ws1, bs1, Ws2, bs2, n);
    k_colmax<0><<<256, 256>>>(n);
    k_redmax<<<1, 32>>>();
    k_colsum<0><<<256, 256>>>(n);
    k_redsum<<<1, 32>>>(0);
    k_start<<<256, 256>>>(o_sn, o_sp, n);

    // --- end head (second half of `combined` duplicates rows 0..9) ---
    k_head<24, 1><<<gb(n, 128), 128>>>(We1, be1, We2, be2, n);
    k_colmax<1><<<256, 256>>>(n);
    k_redmax<<<1, 32>>>();
    k_colsum<1><<<256, 256>>>(n);
    k_redsum<<<1, 32>>>(1);
    k_end1<<<256, 256>>>(o_en, o_ep, n);
    k_end2<<<256, 256>>>(o_en, o_ep, n);
}

// round 16
// speedup vs baseline: 1.2621x; 1.0034x over previous
#include <cuda_runtime.h>
#include <cstdint>
#include <math.h>

#define DINL __device__ __forceinline__

// ---------------- problem constants ----------------
constexpr int NG   = 100000;     // graph nodes
constexpr int NC   = 10;         // candidates
constexpr int NTOT = NG + NC;    // 100010
constexpr int FIN  = 128;
constexpr int T    = 10;         // types
constexpr int EMAX = 6400000;
constexpr int SC_B = (NTOT + 255) / 256;   // 391 scan blocks

// ---------------- scratch (__device__ globals; no allocation) ----------------
__device__ __align__(128) float g_hA[NTOT * 32];
__device__ __align__(128) float g_hB[NTOT * 32];
__device__ __align__(128) float g_t [NTOT * 32];   // t' = (h@W)*dinv[row]
__device__ float g_dinv[NTOT];
__device__ int   g_icnt[NTOT];    // in-degree (without self loop)
__device__ int   g_off [NTOT];    // CSR row offsets (by dst)
__device__ int   g_cur [NTOT];    // fill cursors
__device__ int   g_csrc[EMAX];    // CSR column = src node
__device__ int   g_bsum[512];
__device__ int   g_bpre[512];
__device__ __align__(128) float g_zs[NTOT * T];
__device__ __align__(128) float g_ze[NTOT * T];
__device__ float g_part[256 * T];
__device__ float g_M[T];
__device__ float g_S[T];
__device__ int   g_cnt[T];
__device__ int   g_sn [NTOT];
__device__ int   g_is64;

// ---------------- TF32 rounding (match XLA default f32 matmul) -------
DINL float tf32r(float x) {
    uint32_t r;
    asm("cvt.rna.tf32.f32 %0, %1;" : "=r"(r) : "f"(x));
    return __uint_as_float(r);
}

// ---------------- threefry2x32 (exact JAX, partitionable) ----------------
struct KP { uint32_t a, b; };

__host__ __device__ constexpr uint32_t rotl32(uint32_t x, int r) {
    return (x << r) | (x >> (32 - r));
}

__host__ __device__ constexpr KP tf2x32(uint32_t k0, uint32_t k1, uint32_t c0, uint32_t c1) {
    uint32_t ks0 = k0, ks1 = k1, ks2 = k0 ^ k1 ^ 0x1BD11BDAu;
    uint32_t x0 = c0 + ks0, x1 = c1 + ks1;
    const int r0[4] = {13, 15, 26, 6};
    const int r1[4] = {17, 29, 16, 24};
    for (int i = 0; i < 4; i++) { x0 += x1; x1 = rotl32(x1, r0[i]); x1 ^= x0; }
    x0 += ks1; x1 += ks2 + 1u;
    for (int i = 0; i < 4; i++) { x0 += x1; x1 = rotl32(x1, r1[i]); x1 ^= x0; }
    x0 += ks2; x1 += ks0 + 2u;
    for (int i = 0; i < 4; i++) { x0 += x1; x1 = rotl32(x1, r0[i]); x1 ^= x0; }
    x0 += ks0; x1 += ks1 + 3u;
    for (int i = 0; i < 4; i++) { x0 += x1; x1 = rotl32(x1, r1[i]); x1 ^= x0; }
    x0 += ks1; x1 += ks2 + 4u;
    for (int i = 0; i < 4; i++) { x0 += x1; x1 = rotl32(x1, r0[i]); x1 ^= x0; }
    x0 += ks2; x1 += ks0 + 5u;
    return {x0, x1};
}

constexpr KP SK0 = tf2x32(0u, 42u, 0u, 0u);   // k1
constexpr KP SK1 = tf2x32(0u, 42u, 0u, 1u);   // k2
constexpr uint32_t K1A = SK0.a, K1B = SK0.b;
constexpr uint32_t K2A = SK1.a, K2B = SK1.b;

constexpr float JAX_TINY = 1.17549435e-38f;

DINL float jax_gumbel(uint32_t k0, uint32_t k1, uint32_t idx) {
    KP o = tf2x32(k0, k1, 0u, idx);
    uint32_t bits = o.a ^ o.b;
    float f = __uint_as_float((bits >> 9) | 0x3f800000u) - 1.0f;   // [0,1)
    float u = fmaxf(JAX_TINY, f + JAX_TINY);
    double l1 = -log((double)u);
    return (float)(-log(l1));
}

// ---------------- edge-index access (int32/int64 agnostic) ----------------
DINL int ei_at(const void* eiv, size_t idx) {
    if (g_is64) return (int)((const long long*)eiv)[idx];
    return ((const int*)eiv)[idx];
}

// ---------------- CSR build ----------------
__global__ void k_detect(const int* __restrict__ cidx) {
    g_is64 = (cidx[1] == 0) ? 1 : 0;
}

__global__ void k_zcnt(int n) {
    int i = blockIdx.x * blockDim.x + threadIdx.x;
    if (i < n) g_icnt[i] = 0;
    if (i < T) g_cnt[i] = 0;
}

__global__ void k_hist(const void* __restrict__ eiv, int e) {
    int i = blockIdx.x * blockDim.x + threadIdx.x;
    if (i >= e) return;
    atomicAdd(&g_icnt[ei_at(eiv, (size_t)e + i)], 1);
}

__global__ void k_scansum(int n) {               // grid SC_B, block 256
    __shared__ int sm[256];
    int i = blockIdx.x * 256 + threadIdx.x;
    sm[threadIdx.x] = (i < n) ? g_icnt[i] : 0;
    __syncthreads();
    for (int s = 128; s > 0; s >>= 1) {
        if (threadIdx.x < s) sm[threadIdx.x] += sm[threadIdx.x + s];
        __syncthreads();
    }
    if (threadIdx.x == 0) g_bsum[blockIdx.x] = sm[0];
}

__global__ void k_scanblk(int nb) {
    if (threadIdx.x == 0) {
        int acc = 0;
        for (int b = 0; b < nb; b++) { g_bpre[b] = acc; acc += g_bsum[b]; }
    }
}

// offsets + cursors + dinv in one pass
__global__ void k_scanout(int n) {               // grid SC_B, block 256
    __shared__ int sm[256];
    int i = blockIdx.x * 256 + threadIdx.x;
    int v = (i < n) ? g_icnt[i] : 0;
    sm[threadIdx.x] = v;
    __syncthreads();
    for (int s = 1; s < 256; s <<= 1) {
        int t = (threadIdx.x >= s) ? sm[threadIdx.x - s] : 0;
        __syncthreads();
        sm[threadIdx.x] += t;
        __syncthreads();
    }
    if (i < n) {
        int off = g_bpre[blockIdx.x] + sm[threadIdx.x] - v;   // exclusive
        g_off[i] = off;
        g_cur[i] = off;
        g_dinv[i] = rsqrtf((float)v + 1.0f);
    }
}

__global__ void k_fill(const void* __restrict__ eiv, int e) {
    int i = blockIdx.x * blockDim.x + threadIdx.x;
    if (i >= e) return;
    int s = ei_at(eiv, i);
    int d = ei_at(eiv, (size_t)e + i);
    int pos = atomicAdd(&g_cur[d], 1);
    g_csrc[pos] = s;
}

// ---------------- GCN layers ----------------
// t = hin @ W   (optionally * dinv[row]); float4 loads; TF32 operand rounding.
// SRCSEL: 0 = concat(x,cand), 1 = g_hA, 2 = g_hB. SCALE: mult by dinv at end.
template <int Fin, int Fout, int SRCSEL, int SCALE>
__global__ void k_gemm(const float* __restrict__ x, const float* __restrict__ cand,
                       const float* __restrict__ W, int n) {
    __shared__ float sW[Fin * Fout];
    for (int i = threadIdx.x; i < Fin * Fout; i += blockDim.x) sW[i] = tf32r(W[i]);
    __syncthreads();
    int row = blockIdx.x * blockDim.x + threadIdx.x;
    if (row >= n) return;
    const float* src;
    if (SRCSEL == 0) src = (row >= NG) ? (cand + (size_t)(row - NG) * Fin)
                                       : (x + (size_t)row * Fin);
    else if (SRCSEL == 1) src = g_hA + (size_t)row * Fin;
    else                  src = g_hB + (size_t)row * Fin;
    float acc[Fout];
#pragma unroll
    for (int f = 0; f < Fout; f++) acc[f] = 0.0f;
    const float4* src4 = (const float4*)src;
#pragma unroll
    for (int k4 = 0; k4 < Fin / 4; k4++) {
        float4 xv = src4[k4];
        float xs[4] = {tf32r(xv.x), tf32r(xv.y), tf32r(xv.z), tf32r(xv.w)};
#pragma unroll
        for (int q = 0; q < 4; q++) {
            int k = k4 * 4 + q;
#pragma unroll
            for (int f = 0; f < Fout; f++) acc[f] = fmaf(xs[q], sW[k * Fout + f], acc[f]);
        }
    }
    float dv = SCALE ? g_dinv[row] : 1.0f;
#pragma unroll
    for (int f = 0; f < Fout; f++)
        g_t[(size_t)row * Fout + f] = SCALE ? acc[f] * dv : acc[f];
}

// t[row,:] *= dinv[row]  (used when layer-1 gemm ran before dinv was ready)
template <int F>
__global__ void k_scale(int n) {
    int i = blockIdx.x * blockDim.x + threadIdx.x;
    if (i < n * F) g_t[i] *= g_dinv[i / F];
}

DINL void f4add(float4& a, const float4& v) {
    a.x += v.x; a.y += v.y; a.z += v.z; a.w += v.w;
}

// out[d] = dinv[d] * (sum_{s in N(d)} t'[s] + t'[d]) + b   (pull; no atomics)
// 4x unrolled, two accumulator chains for MLP.
template <int F, int DSTSEL>
__global__ void k_gather(const float* __restrict__ b, int n) {
    constexpr int PER = F / 4;
    int tid = blockIdx.x * blockDim.x + threadIdx.x;
    if (tid >= n * PER) return;
    int d = tid / PER, c = tid - d * PER;
    int j   = g_off[d];
    int end = j + g_icnt[d];
    float4 a0 = make_float4(0.f, 0.f, 0.f, 0.f);
    float4 a1 = make_float4(0.f, 0.f, 0.f, 0.f);
    for (; j + 4 <= end; j += 4) {
        int s0 = __ldg(&g_csrc[j + 0]);
        int s1 = __ldg(&g_csrc[j + 1]);
        int s2 = __ldg(&g_csrc[j + 2]);
        int s3 = __ldg(&g_csrc[j + 3]);
        float4 v0 = *(const float4*)(g_t + (size_t)s0 * F + c * 4);
        float4 v1 = *(const float4*)(g_t + (size_t)s1 * F + c * 4);
        float4 v2 = *(const float4*)(g_t + (size_t)s2 * F + c * 4);
        float4 v3 = *(const float4*)(g_t + (size_t)s3 * F + c * 4);
        f4add(a0, v0); f4add(a1, v1); f4add(a0, v2); f4add(a1, v3);
    }
    for (; j < end; j++) {
        int s = __ldg(&g_csrc[j]);
        f4add(a0, *(const float4*)(g_t + (size_t)s * F + c * 4));
    }
    f4add(a0, a1);
    float4 tv = *(const float4*)(g_t + (size_t)d * F + c * 4);
    float dv = g_dinv[d];
    float* dst = (DSTSEL == 1) ? g_hA : g_hB;
    float4 o;
    o.x = (a0.x + tv.x) * dv + b[c * 4 + 0];
    o.y = (a0.y + tv.y) * dv + b[c * 4 + 1];
    o.z = (a0.z + tv.z) * dv + b[c * 4 + 2];
    o.w = (a0.w + tv.w) * dv + b[c * 4 + 3];
    *(float4*)(dst + (size_t)d * F + c * 4) = o;
}

// ---------------- heads + softmax + sampling ----------------
template <int H, int ZSEL>
__global__ void k_head(const float* __restrict__ W1, const float* __restrict__ b1,
                       const float* __restrict__ W2, const float* __restrict__ b2, int n) {
    __shared__ float sW1[32 * H], sB1[H], sW2[H * T], sB2[T];
    for (int i = threadIdx.x; i < 32 * H; i += blockDim.x) sW1[i] = tf32r(W1[i]);
    for (int i = threadIdx.x; i < H * T;  i += blockDim.x) sW2[i] = tf32r(W2[i]);
    if (threadIdx.x < H) sB1[threadIdx.x] = b1[threadIdx.x];
    if (threadIdx.x < T) sB2[threadIdx.x] = b2[threadIdx.x];
    __syncthreads();
    int row = blockIdx.x * blockDim.x + threadIdx.x;
    if (row >= n) return;
    float hv[32];
    const float4* h4 = (const float4*)(g_hA + (size_t)row * 32);
#pragma unroll
    for (int k4 = 0; k4 < 8; k4++) {
        float4 v = h4[k4];
        hv[k4 * 4 + 0] = tf32r(v.x); hv[k4 * 4 + 1] = tf32r(v.y);
        hv[k4 * 4 + 2] = tf32r(v.z); hv[k4 * 4 + 3] = tf32r(v.w);
    }
    float s1[H];
#pragma unroll
    for (int j = 0; j < H; j++) {
        float a = 0.0f;
#pragma unroll
        for (int k = 0; k < 32; k++) a = fmaf(hv[k], sW1[k * H + j], a);
        a += sB1[j];
        s1[j] = tf32r(fminf(fmaxf(a, 0.0f), 6.0f));
    }
    float* z = (ZSEL == 0) ? g_zs : g_ze;
#pragma unroll
    for (int t = 0; t < T; t++) {
        float a = 0.0f;
#pragma unroll
        for (int j = 0; j < H; j++) a = fmaf(s1[j], sW2[j * T + t], a);
        z[(size_t)row * T + t] = a + sB2[t];
    }
}

template <int ZSEL>
__global__ void k_colmax(int n) {
    const float* z = (ZSEL == 0) ? g_zs : g_ze;
    float m[T];
#pragma unroll
    for (int t = 0; t < T; t++) m[t] = -3.402823466e38f;
    for (int row = blockIdx.x * blockDim.x + threadIdx.x; row < n;
         row += gridDim.x * blockDim.x)
#pragma unroll
        for (int t = 0; t < T; t++) m[t] = fmaxf(m[t], z[(size_t)row * T + t]);
    __shared__ float sm[256 * T];
#pragma unroll
    for (int t = 0; t < T; t++) sm[t * 256 + threadIdx.x] = m[t];
    __syncthreads();
    for (int s = 128; s > 0; s >>= 1) {
        if (threadIdx.x < s)
#pragma unroll
            for (int t = 0; t < T; t++)
                sm[t * 256 + threadIdx.x] =
                    fmaxf(sm[t * 256 + threadIdx.x], sm[t * 256 + threadIdx.x + s]);
        __syncthreads();
    }
    if (threadIdx.x == 0)
#pragma unroll
        for (int t = 0; t < T; t++) g_part[blockIdx.x * T + t] = sm[t * 256];
}

__global__ void k_redmax() {
    int t = threadIdx.x;
    if (t < T) {
        float m = -3.402823466e38f;
        for (int b = 0; b < 256; b++) m = fmaxf(m, g_part[b * T + t]);
        g_M[t] = m;
    }
}

DINL float pexp(float x) { return (float)exp((double)x); }

template <int ZSEL>
__global__ void k_colsum(int n) {
    const float* z = (ZSEL == 0) ? g_zs : g_ze;
    float M[T], s[T];
#pragma unroll
    for (int t = 0; t < T; t++) { M[t] = g_M[t]; s[t] = 0.0f; }
    for (int row = blockIdx.x * blockDim.x + threadIdx.x; row < n;
         row += gridDim.x * blockDim.x)
#pragma unroll
        for (int t = 0; t < T; t++) s[t] += pexp(z[(size_t)row * T + t] - M[t]);
    __shared__ float sm[256 * T];
#pragma unroll
    for (int t = 0; t < T; t++) sm[t * 256 + threadIdx.x] = s[t];
    __syncthreads();
    for (int st = 128; st > 0; st >>= 1) {
        if (threadIdx.x < st)
#pragma unroll
            for (int t = 0; t < T; t++)
                sm[t * 256 + threadIdx.x] += sm[t * 256 + threadIdx.x + st];
        __syncthreads();
    }
    if (threadIdx.x == 0)
#pragma unroll
        for (int t = 0; t < T; t++) g_part[blockIdx.x * T + t] = sm[t * 256];
}

__global__ void k_redsum(int addCand) {
    int t = threadIdx.x;
    if (t < T) {
        float s = 0.0f;
        for (int b = 0; b < 256; b++) s += g_part[b * T + t];
        if (addCand)
            for (int c = 0; c < T; c++)
                s += (float)g_cnt[c] * pexp(g_ze[c * T + t] - g_M[t]);
        g_S[t] = s;
    }
}

DINL void prob_logp(float zmM, float S, float& pf, float& lpf) {
    double pd = exp((double)zmM) / (double)S;
    pf = (float)pd;
    lpf = (float)log(pd);
}

__global__ void k_start(float* __restrict__ out_node, float* __restrict__ out_probs,
                        int n) {
    __shared__ int hist[T];
    if (threadIdx.x < T) hist[threadIdx.x] = 0;
    __syncthreads();
    float M[T], S[T];
#pragma unroll
    for (int t = 0; t < T; t++) { M[t] = g_M[t]; S[t] = g_S[t]; }
    const float lp10 = (float)log(1e-10);
    int row = blockIdx.x * blockDim.x + threadIdx.x;
    if (row < n) {
        float best = -3.402823466e38f; int bi = 0;
        uint32_t base = (uint32_t)row * T;
#pragma unroll
        for (int t = 0; t < T; t++) {
            float pf, lpf;
            prob_logp(g_zs[(size_t)row * T + t] - M[t], S[t], pf, lpf);
            if (row >= NG) { pf = 1e-10f; lpf = lp10; }
            out_probs[(size_t)row * T + t] = pf;
            float v = jax_gumbel(K1A, K1B, base + t) + lpf;
            if (v > best) { best = v; bi = t; }
        }
        out_node[row] = (float)bi;
        g_sn[row] = bi;
        atomicAdd(&hist[bi], 1);
    }
    __syncthreads();
    if (threadIdx.x < T) atomicAdd(&g_cnt[threadIdx.x], hist[threadIdx.x]);
}

__global__ void k_end1(float* __restrict__ out_node, float* __restrict__ out_probs,
                       int n) {
    float M[T], S[T]; int zr[T];
#pragma unroll
    for (int t = 0; t < T; t++) { M[t] = g_M[t]; S[t] = g_S[t]; zr[t] = (g_cnt[t] > 0); }
    const float lp10 = (float)log(1e-10);
    int row = blockIdx.x * blockDim.x + threadIdx.x;
    if (row >= n) return;
    float best = -3.402823466e38f; int bi = 0;
    uint32_t base = (uint32_t)row * T;
    bool zero_row = (row < T) && zr[row];
#pragma unroll
    for (int t = 0; t < T; t++) {
        float pf, lpf;
        prob_logp(g_ze[(size_t)row * T + t] - M[t], S[t], pf, lpf);
        if (zero_row) { pf = 1e-10f; lpf = lp10; }
        out_probs[(size_t)row * T + t] = pf;
        float v = jax_gumbel(K2A, K2B, base + t) + lpf;
        if (v > best) { best = v; bi = t; }
    }
    out_node[row] = (float)bi;
}

__global__ void k_end2(float* __restrict__ out_node, float* __restrict__ out_probs,
                       int n) {
    __shared__ float sp[T * T];
    __shared__ float sl[T * T];
    if (threadIdx.x < T * T) {
        int c = threadIdx.x / T, t = threadIdx.x - c * T;
        float pf, lpf;
        prob_logp(g_ze[c * T + t] - g_M[t], g_S[t], pf, lpf);
        sp[threadIdx.x] = pf;
        sl[threadIdx.x] = lpf;
    }
    __syncthreads();
    int i = blockIdx.x * blockDim.x + threadIdx.x;
    if (i >= n) return;
    int row = n + i;
    int sn = g_sn[i];
    float best = -3.402823466e38f; int bi = 0;
    uint32_t base = (uint32_t)row * T;
#pragma unroll
    for (int t = 0; t < T; t++) {
        out_probs[(size_t)row * T + t] = sp[sn * T + t];
        float v = jax_gumbel(K2A, K2B, base + t) + sl[sn * T + t];
        if (v > best) { best = v; bi = t; }
    }
    out_node[row] = (float)bi;
}

// ---------------- launch ----------------
extern "C" void kernel_launch(void* const* d_in, const int* in_sizes, int n_in,
                              void* d_out, int out_size) {
    const float* x    = (const float*)d_in[0];
    const float* cand = (const float*)d_in[1];
    const void*  ei   = d_in[2];
    const int*   cidx = (const int*)d_in[3];
    const float *W1 = (const float*)d_in[4],  *b1 = (const float*)d_in[5];
    const float *W2 = (const float*)d_in[6],  *b2 = (const float*)d_in[7];
    const float *W3 = (const float*)d_in[8],  *b3 = (const float*)d_in[9];
    const float *Ws1 = (const float*)d_in[10], *bs1 = (const float*)d_in[11];
    const float *Ws2 = (const float*)d_in[12], *bs2 = (const float*)d_in[13];
    const float *We1 = (const float*)d_in[14], *be1 = (const float*)d_in[15];
    const float *We2 = (const float*)d_in[16], *be2 = (const float*)d_in[17];

    int n = in_sizes[0] / FIN + in_sizes[1] / FIN;   // 100010
    int E = in_sizes[2] / 2;

    float* out   = (float*)d_out;
    float* o_sn  = out;
    float* o_en  = out + n;
    float* o_sp  = out + 3 * (size_t)n;
    float* o_ep  = out + 3 * (size_t)n + (size_t)T * n;

    const int TB = 256;
    auto gb = [](long long w, int tb) { return (unsigned)((w + tb - 1) / tb); };

    // side stream + events, created once on the (uncaptured) correctness call
    static cudaStream_t s2 = nullptr;
    static cudaEvent_t evFork = nullptr, evGemm1 = nullptr;
    if (!s2) {
        cudaStreamCreateWithFlags(&s2, cudaStreamNonBlocking);
        cudaEventCreateWithFlags(&evFork, cudaEventDisableTiming);
        cudaEventCreateWithFlags(&evGemm1, cudaEventDisableTiming);
    }

    // --- fork: layer-1 GEMM (dinv-free) overlaps the whole CSR build ---
    cudaEventRecord(evFork, 0);
    cudaStreamWaitEvent(s2, evFork, 0);
    k_gemm<128, 16, 0, 0><<<gb(n, 128), 128, 0, s2>>>(x, cand, W1, n);
    cudaEventRecord(evGemm1, s2);

    // --- CSR build (main stream) ---
    k_detect<<<1, 1>>>(cidx);
    k_zcnt<<<gb(n, TB), TB>>>(n);
    k_hist<<<gb(E, TB), TB>>>(ei, E);
    k_scansum<<<SC_B, 256>>>(n);
    k_scanblk<<<1, 32>>>(SC_B);
    k_scanout<<<SC_B, 256>>>(n);     // offsets + cursors + dinv
    k_fill<<<gb(E, TB), TB>>>(ei, E);

    // --- join, then scale layer-1 t by dinv and gather ---
    cudaStreamWaitEvent(0, evGemm1, 0);
    k_scale<16><<<gb((long long)n * 16, TB), TB>>>(n);
    k_gather<16, 1><<<gb((long long)n * 4, TB), TB>>>(b1, n);

    // --- layer 2: hA -> hB  (16 -> 24) ---
    k_gemm<16, 24, 1, 1><<<gb(n, 128), 128>>>(nullptr, nullptr, W2, n);
    k_gather<24, 2><<<gb((long long)n * 6, TB), TB>>>(b2, n);

    // --- layer 3: hB -> hA  (24 -> 32) ---
    k_gemm<24, 32, 2, 1><<<gb(n, 128), 128>>>(nullptr, nullptr, W3, n);
    k_gather<32, 1><<<gb((long long)n * 8, TB), TB>>>(b3, n);

    // --- start head ---
    k_head<16, 0><<<gb(n, 128), 128>>>(Ws1, bs1, Ws2, bs2, n);
    k_colmax<0><<<256, 256>>>(n);
    k_redmax<<<1, 32>>>();
    k_colsum<0><<<256, 256>>>(n);
    k_redsum<<<1, 32>>>(0);
    k_start<<<gb(n, TB), TB>>>(o_sn, o_sp, n);

    // --- end head (second half of `combined` duplicates rows 0..9) ---
    k_head<24, 1><<<gb(n, 128), 128>>>(We1, be1, We2, be2, n);
    k_colmax<1><<<256, 256>>>(n);
    k_redmax<<<1, 32>>>();
    k_colsum<1><<<256, 256>>>(n);
    k_redsum<<<1, 32>>>(1);
    k_end1<<<gb(n, TB), TB>>>(o_en, o_ep, n);
    k_end2<<<gb(n, TB), TB>>>(o_en, o_ep, n);
}

// round 17
// speedup vs baseline: 3.1314x; 2.4812x over previous
#include <cuda_runtime.h>
#include <cstdint>
#include <math.h>

#define DINL __device__ __forceinline__

// ---------------- problem constants ----------------
constexpr int NG   = 100000;     // graph nodes
constexpr int NC   = 10;         // candidates
constexpr int NTOT = NG + NC;    // 100010
constexpr int FIN  = 128;
constexpr int T    = 10;         // types
constexpr int EMAX = 6400000;
constexpr int SC_B = (NTOT + 255) / 256;   // 391 scan blocks

// ---------------- scratch (__device__ globals; no allocation) ----------------
__device__ __align__(128) float g_hA[NTOT * 32];
__device__ __align__(128) float g_hB[NTOT * 32];
__device__ __align__(128) float g_t [NTOT * 32];   // t' = (h@W)*dinv[row]
__device__ float g_dinv[NTOT];
__device__ int   g_icnt[NTOT];    // in-degree (without self loop)
__device__ int   g_off [NTOT];    // CSR row offsets (by dst)
__device__ int   g_cur [NTOT];    // fill cursors
__device__ int   g_csrc[EMAX];    // CSR column = src node
__device__ int   g_bsum[512];
__device__ int   g_bpre[512];
__device__ __align__(128) float g_zs[NTOT * T];
__device__ __align__(128) float g_ze[NTOT * T];
__device__ float g_part[256 * T];
__device__ float g_M[T];
__device__ float g_S[T];
__device__ int   g_cnt[T];
__device__ int   g_sn [NTOT];
__device__ int   g_is64;

// ---------------- TF32 rounding (match XLA default f32 matmul) -------
DINL float tf32r(float x) {
    uint32_t r;
    asm("cvt.rna.tf32.f32 %0, %1;" : "=r"(r) : "f"(x));
    return __uint_as_float(r);
}

// ---------------- float-float (double-single) arithmetic ----------------
// ~1e-9 relative accuracy; fmaf-based, immune to --use_fast_math.
struct DF { float h, l; };

DINL DF two_sum(float a, float b) {
    float s = a + b;
    float bb = s - a;
    float e = (a - (s - bb)) + (b - bb);
    return {s, e};
}
DINL DF quick2(float a, float b) {        // requires |a| >= |b| (renorm)
    float s = a + b;
    float e = b - (s - a);
    return {s, e};
}
DINL DF two_prod(float a, float b) {
    float p = a * b;
    float e = fmaf(a, b, -p);
    return {p, e};
}
DINL DF df_add(DF a, DF b) {
    DF s = two_sum(a.h, b.h);
    s.l += a.l + b.l;
    return quick2(s.h, s.l);
}
DINL DF df_addf(DF a, float b) {
    DF s = two_sum(a.h, b);
    s.l += a.l;
    return quick2(s.h, s.l);
}
DINL DF df_mul(DF a, DF b) {
    DF p = two_prod(a.h, b.h);
    p.l += a.h * b.l + a.l * b.h;
    return quick2(p.h, p.l);
}
DINL DF df_mulf(DF a, float b) {
    DF p = two_prod(a.h, b);
    p.l += a.l * b;
    return quick2(p.h, p.l);
}
// self-correcting division (approx q0 refined via exact fma remainder)
DINL DF df_div(DF a, DF b) {
    float q0 = a.h / b.h;
    DF p = two_prod(q0, b.h);
    float r = ((a.h - p.h) - p.l) + a.l - q0 * b.l;
    float q1 = r / b.h;
    return quick2(q0, q1);
}

// ln2 = LN2H + LN2L (double-single split)
constexpr float LN2H = 0.69314718246459960938f;
constexpr float LN2L = -1.9046542e-9f;

// log(x) for x.h in (1e-38, 1e38), df accurate ~5e-9 relative
DINL DF df_log(DF x) {
    int ix = __float_as_int(x.h);
    int e = ((ix >> 23) & 0xFF) - 127;
    float m = __int_as_float((ix & 0x007FFFFF) | 0x3F800000);   // [1,2)
    if (m > 1.4142135f) { m *= 0.5f; e += 1; }                   // [0.7071,1.4142)
    float sc = __int_as_float((127 - e) << 23);                  // 2^-e (|e|<90 here)
    float ml = x.l * sc;
    DF num = two_sum(m - 1.0f, ml);            // m-1 exact (Sterbenz)
    DF den = df_addf(two_sum(m, 1.0f), ml);
    DF s = df_div(num, den);                   // s = (m-1)/(m+1), |s|<=0.1716
    float s2 = s.h * s.h;
    float P = s2*(0.33333334f + s2*(0.2f + s2*(0.14285715f + s2*(0.11111111f +
              s2*(0.090909094f + s2*0.07692308f)))));
    DF res = df_add(df_mulf(s, 2.0f), (DF){2.0f * s.h * P, 0.0f});
    res = df_add(df_mulf((DF){LN2H, LN2L}, (float)e), res);
    return res;
}

// exp(x) for x.h in [-88, 88], df accurate ~5e-9 relative
DINL DF df_exp(DF x) {
    float kf = rintf(x.h * 1.442695041f);
    DF r = df_add(x, df_mulf((DF){-LN2H, -LN2L}, kf));           // |r| <= 0.347
    DF r2 = df_mul(r, r);
    float rh = r.h;
    float C = 0.16666667f + rh*(0.041666668f + rh*(0.008333334f + rh*(0.0013888889f +
              rh*(1.984127e-4f + rh*(2.4801588e-5f + rh*2.7557319e-6f)))));
    float r3C = r2.h * rh * C;
    DF acc = df_addf(r, 1.0f);
    acc = df_add(acc, df_mulf(r2, 0.5f));
    acc = df_addf(acc, r3C);
    int k = (int)kf;
    acc.h = ldexpf(acc.h, k);
    acc.l = ldexpf(acc.l, k);
    return acc;
}

DINL float pexp(float x) { DF e = df_exp({x, 0.0f}); return e.h + e.l; }

// ---------------- threefry2x32 (exact JAX, partitionable) ----------------
struct KP { uint32_t a, b; };

__host__ __device__ constexpr uint32_t rotl32(uint32_t x, int r) {
    return (x << r) | (x >> (32 - r));
}

__host__ __device__ constexpr KP tf2x32(uint32_t k0, uint32_t k1, uint32_t c0, uint32_t c1) {
    uint32_t ks0 = k0, ks1 = k1, ks2 = k0 ^ k1 ^ 0x1BD11BDAu;
    uint32_t x0 = c0 + ks0, x1 = c1 + ks1;
    const int r0[4] = {13, 15, 26, 6};
    const int r1[4] = {17, 29, 16, 24};
    for (int i = 0; i < 4; i++) { x0 += x1; x1 = rotl32(x1, r0[i]); x1 ^= x0; }
    x0 += ks1; x1 += ks2 + 1u;
    for (int i = 0; i < 4; i++) { x0 += x1; x1 = rotl32(x1, r1[i]); x1 ^= x0; }
    x0 += ks2; x1 += ks0 + 2u;
    for (int i = 0; i < 4; i++) { x0 += x1; x1 = rotl32(x1, r0[i]); x1 ^= x0; }
    x0 += ks0; x1 += ks1 + 3u;
    for (int i = 0; i < 4; i++) { x0 += x1; x1 = rotl32(x1, r1[i]); x1 ^= x0; }
    x0 += ks1; x1 += ks2 + 4u;
    for (int i = 0; i < 4; i++) { x0 += x1; x1 = rotl32(x1, r0[i]); x1 ^= x0; }
    x0 += ks2; x1 += ks0 + 5u;
    return {x0, x1};
}

constexpr KP SK0 = tf2x32(0u, 42u, 0u, 0u);   // k1
constexpr KP SK1 = tf2x32(0u, 42u, 0u, 1u);   // k2
constexpr uint32_t K1A = SK0.a, K1B = SK0.b;
constexpr uint32_t K2A = SK1.a, K2B = SK1.b;

constexpr float JAX_TINY = 1.17549435e-38f;

// gumbel = -log(-log(uniform(tiny,1))) — l1 kept in df between the two logs
DINL float jax_gumbel(uint32_t k0, uint32_t k1, uint32_t idx) {
    KP o = tf2x32(k0, k1, 0u, idx);
    uint32_t bits = o.a ^ o.b;
    float f = __uint_as_float((bits >> 9) | 0x3f800000u) - 1.0f;   // [0,1)
    float u = fmaxf(JAX_TINY, f + JAX_TINY);
    DF l1 = df_log({u, 0.0f});
    l1.h = -l1.h; l1.l = -l1.l;                 // l1 in (1.19e-7, 87.4)
    DF l2 = df_log(l1);
    return -(l2.h + l2.l);
}

// p = exp(zmM)/S rounded to f32, lp = log(p) (mirrors XLA's fp32 op chain)
DINL void prob_logp(float zmM, float S, float& pf, float& lpf) {
    DF e = df_exp({zmM, 0.0f});
    DF q = df_div(e, {S, 0.0f});
    pf = q.h + q.l;
    DF lg = df_log({pf, 0.0f});
    lpf = lg.h + lg.l;
}

// ---------------- edge-index access (int32/int64 agnostic) ----------------
DINL int ei_at(const void* eiv, size_t idx) {
    if (g_is64) return (int)((const long long*)eiv)[idx];
    return ((const int*)eiv)[idx];
}

// ---------------- CSR build ----------------
__global__ void k_detect(const int* __restrict__ cidx) {
    g_is64 = (cidx[1] == 0) ? 1 : 0;
}

__global__ void k_zcnt(int n) {
    int i = blockIdx.x * blockDim.x + threadIdx.x;
    if (i < n) g_icnt[i] = 0;
    if (i < T) g_cnt[i] = 0;
}

__global__ void k_hist(const void* __restrict__ eiv, int e) {
    int i = blockIdx.x * blockDim.x + threadIdx.x;
    if (i >= e) return;
    atomicAdd(&g_icnt[ei_at(eiv, (size_t)e + i)], 1);
}

__global__ void k_scansum(int n) {               // grid SC_B, block 256
    __shared__ int sm[256];
    int i = blockIdx.x * 256 + threadIdx.x;
    sm[threadIdx.x] = (i < n) ? g_icnt[i] : 0;
    __syncthreads();
    for (int s = 128; s > 0; s >>= 1) {
        if (threadIdx.x < s) sm[threadIdx.x] += sm[threadIdx.x + s];
        __syncthreads();
    }
    if (threadIdx.x == 0) g_bsum[blockIdx.x] = sm[0];
}

__global__ void k_scanblk(int nb) {
    if (threadIdx.x == 0) {
        int acc = 0;
        for (int b = 0; b < nb; b++) { g_bpre[b] = acc; acc += g_bsum[b]; }
    }
}

// offsets + cursors + dinv in one pass
__global__ void k_scanout(int n) {               // grid SC_B, block 256
    __shared__ int sm[256];
    int i = blockIdx.x * 256 + threadIdx.x;
    int v = (i < n) ? g_icnt[i] : 0;
    sm[threadIdx.x] = v;
    __syncthreads();
    for (int s = 1; s < 256; s <<= 1) {
        int t = (threadIdx.x >= s) ? sm[threadIdx.x - s] : 0;
        __syncthreads();
        sm[threadIdx.x] += t;
        __syncthreads();
    }
    if (i < n) {
        int off = g_bpre[blockIdx.x] + sm[threadIdx.x] - v;   // exclusive
        g_off[i] = off;
        g_cur[i] = off;
        g_dinv[i] = rsqrtf((float)v + 1.0f);
    }
}

__global__ void k_fill(const void* __restrict__ eiv, int e) {
    int i = blockIdx.x * blockDim.x + threadIdx.x;
    if (i >= e) return;
    int s = ei_at(eiv, i);
    int d = ei_at(eiv, (size_t)e + i);
    int pos = atomicAdd(&g_cur[d], 1);
    g_csrc[pos] = s;
}

// ---------------- GCN layers ----------------
template <int Fin, int Fout, int SRCSEL, int SCALE>
__global__ void k_gemm(const float* __restrict__ x, const float* __restrict__ cand,
                       const float* __restrict__ W, int n) {
    __shared__ float sW[Fin * Fout];
    for (int i = threadIdx.x; i < Fin * Fout; i += blockDim.x) sW[i] = tf32r(W[i]);
    __syncthreads();
    int row = blockIdx.x * blockDim.x + threadIdx.x;
    if (row >= n) return;
    const float* src;
    if (SRCSEL == 0) src = (row >= NG) ? (cand + (size_t)(row - NG) * Fin)
                                       : (x + (size_t)row * Fin);
    else if (SRCSEL == 1) src = g_hA + (size_t)row * Fin;
    else                  src = g_hB + (size_t)row * Fin;
    float acc[Fout];
#pragma unroll
    for (int f = 0; f < Fout; f++) acc[f] = 0.0f;
    const float4* src4 = (const float4*)src;
#pragma unroll
    for (int k4 = 0; k4 < Fin / 4; k4++) {
        float4 xv = src4[k4];
        float xs[4] = {tf32r(xv.x), tf32r(xv.y), tf32r(xv.z), tf32r(xv.w)};
#pragma unroll
        for (int q = 0; q < 4; q++) {
            int k = k4 * 4 + q;
#pragma unroll
            for (int f = 0; f < Fout; f++) acc[f] = fmaf(xs[q], sW[k * Fout + f], acc[f]);
        }
    }
    float dv = SCALE ? g_dinv[row] : 1.0f;
#pragma unroll
    for (int f = 0; f < Fout; f++)
        g_t[(size_t)row * Fout + f] = SCALE ? acc[f] * dv : acc[f];
}

template <int F>
__global__ void k_scale(int n) {
    int i = blockIdx.x * blockDim.x + threadIdx.x;
    if (i < n * F) g_t[i] *= g_dinv[i / F];
}

DINL void f4add(float4& a, const float4& v) {
    a.x += v.x; a.y += v.y; a.z += v.z; a.w += v.w;
}

template <int F, int DSTSEL>
__global__ void k_gather(const float* __restrict__ b, int n) {
    constexpr int PER = F / 4;
    int tid = blockIdx.x * blockDim.x + threadIdx.x;
    if (tid >= n * PER) return;
    int d = tid / PER, c = tid - d * PER;
    int j   = g_off[d];
    int end = j + g_icnt[d];
    float4 a0 = make_float4(0.f, 0.f, 0.f, 0.f);
    float4 a1 = make_float4(0.f, 0.f, 0.f, 0.f);
    for (; j + 4 <= end; j += 4) {
        int s0 = __ldg(&g_csrc[j + 0]);
        int s1 = __ldg(&g_csrc[j + 1]);
        int s2 = __ldg(&g_csrc[j + 2]);
        int s3 = __ldg(&g_csrc[j + 3]);
        float4 v0 = *(const float4*)(g_t + (size_t)s0 * F + c * 4);
        float4 v1 = *(const float4*)(g_t + (size_t)s1 * F + c * 4);
        float4 v2 = *(const float4*)(g_t + (size_t)s2 * F + c * 4);
        float4 v3 = *(const float4*)(g_t + (size_t)s3 * F + c * 4);
        f4add(a0, v0); f4add(a1, v1); f4add(a0, v2); f4add(a1, v3);
    }
    for (; j < end; j++) {
        int s = __ldg(&g_csrc[j]);
        f4add(a0, *(const float4*)(g_t + (size_t)s * F + c * 4));
    }
    f4add(a0, a1);
    float4 tv = *(const float4*)(g_t + (size_t)d * F + c * 4);
    float dv = g_dinv[d];
    float* dst = (DSTSEL == 1) ? g_hA : g_hB;
    float4 o;
    o.x = (a0.x + tv.x) * dv + b[c * 4 + 0];
    o.y = (a0.y + tv.y) * dv + b[c * 4 + 1];
    o.z = (a0.z + tv.z) * dv + b[c * 4 + 2];
    o.w = (a0.w + tv.w) * dv + b[c * 4 + 3];
    *(float4*)(dst + (size_t)d * F + c * 4) = o;
}

// ---------------- heads + softmax + sampling ----------------
template <int H, int ZSEL>
__global__ void k_head(const float* __restrict__ W1, const float* __restrict__ b1,
                       const float* __restrict__ W2, const float* __restrict__ b2, int n) {
    __shared__ float sW1[32 * H], sB1[H], sW2[H * T], sB2[T];
    for (int i = threadIdx.x; i < 32 * H; i += blockDim.x) sW1[i] = tf32r(W1[i]);
    for (int i = threadIdx.x; i < H * T;  i += blockDim.x) sW2[i] = tf32r(W2[i]);
    if (threadIdx.x < H) sB1[threadIdx.x] = b1[threadIdx.x];
    if (threadIdx.x < T) sB2[threadIdx.x] = b2[threadIdx.x];
    __syncthreads();
    int row = blockIdx.x * blockDim.x + threadIdx.x;
    if (row >= n) return;
    float hv[32];
    const float4* h4 = (const float4*)(g_hA + (size_t)row * 32);
#pragma unroll
    for (int k4 = 0; k4 < 8; k4++) {
        float4 v = h4[k4];
        hv[k4 * 4 + 0] = tf32r(v.x); hv[k4 * 4 + 1] = tf32r(v.y);
        hv[k4 * 4 + 2] = tf32r(v.z); hv[k4 * 4 + 3] = tf32r(v.w);
    }
    float s1[H];
#pragma unroll
    for (int j = 0; j < H; j++) {
        float a = 0.0f;
#pragma unroll
        for (int k = 0; k < 32; k++) a = fmaf(hv[k], sW1[k * H + j], a);
        a += sB1[j];
        s1[j] = tf32r(fminf(fmaxf(a, 0.0f), 6.0f));
    }
    float* z = (ZSEL == 0) ? g_zs : g_ze;
#pragma unroll
    for (int t = 0; t < T; t++) {
        float a = 0.0f;
#pragma unroll
        for (int j = 0; j < H; j++) a = fmaf(s1[j], sW2[j * T + t], a);
        z[(size_t)row * T + t] = a + sB2[t];
    }
}

template <int ZSEL>
__global__ void k_colmax(int n) {
    const float* z = (ZSEL == 0) ? g_zs : g_ze;
    float m[T];
#pragma unroll
    for (int t = 0; t < T; t++) m[t] = -3.402823466e38f;
    for (int row = blockIdx.x * blockDim.x + threadIdx.x; row < n;
         row += gridDim.x * blockDim.x)
#pragma unroll
        for (int t = 0; t < T; t++) m[t] = fmaxf(m[t], z[(size_t)row * T + t]);
    __shared__ float sm[256 * T];
#pragma unroll
    for (int t = 0; t < T; t++) sm[t * 256 + threadIdx.x] = m[t];
    __syncthreads();
    for (int s = 128; s > 0; s >>= 1) {
        if (threadIdx.x < s)
#pragma unroll
            for (int t = 0; t < T; t++)
                sm[t * 256 + threadIdx.x] =
                    fmaxf(sm[t * 256 + threadIdx.x], sm[t * 256 + threadIdx.x + s]);
        __syncthreads();
    }
    if (threadIdx.x == 0)
#pragma unroll
        for (int t = 0; t < T; t++) g_part[blockIdx.x * T + t] = sm[t * 256];
}

__global__ void k_redmax() {
    int t = threadIdx.x;
    if (t < T) {
        float m = -3.402823466e38f;
        for (int b = 0; b < 256; b++) m = fmaxf(m, g_part[b * T + t]);
        g_M[t] = m;
    }
}

template <int ZSEL>
__global__ void k_colsum(int n) {
    const float* z = (ZSEL == 0) ? g_zs : g_ze;
    float M[T], s[T];
#pragma unroll
    for (int t = 0; t < T; t++) { M[t] = g_M[t]; s[t] = 0.0f; }
    for (int row = blockIdx.x * blockDim.x + threadIdx.x; row < n;
         row += gridDim.x * blockDim.x)
#pragma unroll
        for (int t = 0; t < T; t++) s[t] += pexp(z[(size_t)row * T + t] - M[t]);
    __shared__ float sm[256 * T];
#pragma unroll
    for (int t = 0; t < T; t++) sm[t * 256 + threadIdx.x] = s[t];
    __syncthreads();
    for (int st = 128; st > 0; st >>= 1) {
        if (threadIdx.x < st)
#pragma unroll
            for (int t = 0; t < T; t++)
                sm[t * 256 + threadIdx.x] += sm[t * 256 + threadIdx.x + st];
        __syncthreads();
    }
    if (threadIdx.x == 0)
#pragma unroll
        for (int t = 0; t < T; t++) g_part[blockIdx.x * T + t] = sm[t * 256];
}

__global__ void k_redsum(int addCand) {
    int t = threadIdx.x;
    if (t < T) {
        float s = 0.0f;
        for (int b = 0; b < 256; b++) s += g_part[b * T + t];
        if (addCand)
            for (int c = 0; c < T; c++)
                s += (float)g_cnt[c] * pexp(g_ze[c * T + t] - g_M[t]);
        g_S[t] = s;
    }
}

__global__ void k_start(float* __restrict__ out_node, float* __restrict__ out_probs,
                        int n) {
    __shared__ int hist[T];
    if (threadIdx.x < T) hist[threadIdx.x] = 0;
    __syncthreads();
    float M[T], S[T];
#pragma unroll
    for (int t = 0; t < T; t++) { M[t] = g_M[t]; S[t] = g_S[t]; }
    const float lp10 = -23.025850929940457f;   // log(1e-10)
    int row = blockIdx.x * blockDim.x + threadIdx.x;
    if (row < n) {
        float best = -3.402823466e38f; int bi = 0;
        uint32_t base = (uint32_t)row * T;
#pragma unroll
        for (int t = 0; t < T; t++) {
            float pf, lpf;
            prob_logp(g_zs[(size_t)row * T + t] - M[t], S[t], pf, lpf);
            if (row >= NG) { pf = 1e-10f; lpf = lp10; }
            out_probs[(size_t)row * T + t] = pf;
            float v = jax_gumbel(K1A, K1B, base + t) + lpf;
            if (v > best) { best = v; bi = t; }
        }
        out_node[row] = (float)bi;
        g_sn[row] = bi;
        atomicAdd(&hist[bi], 1);
    }
    __syncthreads();
    if (threadIdx.x < T) atomicAdd(&g_cnt[threadIdx.x], hist[threadIdx.x]);
}

__global__ void k_end1(float* __restrict__ out_node, float* __restrict__ out_probs,
                       int n) {
    float M[T], S[T]; int zr[T];
#pragma unroll
    for (int t = 0; t < T; t++) { M[t] = g_M[t]; S[t] = g_S[t]; zr[t] = (g_cnt[t] > 0); }
    const float lp10 = -23.025850929940457f;
    int row = blockIdx.x * blockDim.x + threadIdx.x;
    if (row >= n) return;
    float best = -3.402823466e38f; int bi = 0;
    uint32_t base = (uint32_t)row * T;
    bool zero_row = (row < T) && zr[row];
#pragma unroll
    for (int t = 0; t < T; t++) {
        float pf, lpf;
        prob_logp(g_ze[(size_t)row * T + t] - M[t], S[t], pf, lpf);
        if (zero_row) { pf = 1e-10f; lpf = lp10; }
        out_probs[(size_t)row * T + t] = pf;
        float v = jax_gumbel(K2A, K2B, base + t) + lpf;
        if (v > best) { best = v; bi = t; }
    }
    out_node[row] = (float)bi;
}

__global__ void k_end2(float* __restrict__ out_node, float* __restrict__ out_probs,
                       int n) {
    __shared__ float sp[T * T];
    __shared__ float sl[T * T];
    if (threadIdx.x < T * T) {
        int c = threadIdx.x / T, t = threadIdx.x - c * T;
        float pf, lpf;
        prob_logp(g_ze[c * T + t] - g_M[t], g_S[t], pf, lpf);
        sp[threadIdx.x] = pf;
        sl[threadIdx.x] = lpf;
    }
    __syncthreads();
    int i = blockIdx.x * blockDim.x + threadIdx.x;
    if (i >= n) return;
    int row = n + i;
    int sn = g_sn[i];
    float best = -3.402823466e38f; int bi = 0;
    uint32_t base = (uint32_t)row * T;
#pragma unroll
    for (int t = 0; t < T; t++) {
        out_probs[(size_t)row * T + t] = sp[sn * T + t];
        float v = jax_gumbel(K2A, K2B, base + t) + sl[sn * T + t];
        if (v > best) { best = v; bi = t; }
    }
    out_node[row] = (float)bi;
}

// ---------------- launch ----------------
extern "C" void kernel_launch(void* const* d_in, const int* in_sizes, int n_in,
                              void* d_out, int out_size) {
    const float* x    = (const float*)d_in[0];
    const float* cand = (const float*)d_in[1];
    const void*  ei   = d_in[2];
    const int*   cidx = (const int*)d_in[3];
    const float *W1 = (const float*)d_in[4],  *b1 = (const float*)d_in[5];
    const float *W2 = (const float*)d_in[6],  *b2 = (const float*)d_in[7];
    const float *W3 = (const float*)d_in[8],  *b3 = (const float*)d_in[9];
    const float *Ws1 = (const float*)d_in[10], *bs1 = (const float*)d_in[11];
    const float *Ws2 = (const float*)d_in[12], *bs2 = (const float*)d_in[13];
    const float *We1 = (const float*)d_in[14], *be1 = (const float*)d_in[15];
    const float *We2 = (const float*)d_in[16], *be2 = (const float*)d_in[17];

    int n = in_sizes[0] / FIN + in_sizes[1] / FIN;   // 100010
    int E = in_sizes[2] / 2;

    float* out   = (float*)d_out;
    float* o_sn  = out;
    float* o_en  = out + n;
    float* o_sp  = out + 3 * (size_t)n;
    float* o_ep  = out + 3 * (size_t)n + (size_t)T * n;

    const int TB = 256;
    auto gb = [](long long w, int tb) { return (unsigned)((w + tb - 1) / tb); };

    // side stream + events, created once on the (uncaptured) correctness call
    static cudaStream_t s2 = nullptr;
    static cudaEvent_t evFork = nullptr, evGemm1 = nullptr;
    if (!s2) {
        cudaStreamCreateWithFlags(&s2, cudaStreamNonBlocking);
        cudaEventCreateWithFlags(&evFork, cudaEventDisableTiming);
        cudaEventCreateWithFlags(&evGemm1, cudaEventDisableTiming);
    }

    // --- fork: layer-1 GEMM (dinv-free) overlaps the whole CSR build ---
    cudaEventRecord(evFork, 0);
    cudaStreamWaitEvent(s2, evFork, 0);
    k_gemm<128, 16, 0, 0><<<gb(n, 128), 128, 0, s2>>>(x, cand, W1, n);
    cudaEventRecord(evGemm1, s2);

    // --- CSR build (main stream) ---
    k_detect<<<1, 1>>>(cidx);
    k_zcnt<<<gb(n, TB), TB>>>(n);
    k_hist<<<gb(E, TB), TB>>>(ei, E);
    k_scansum<<<SC_B, 256>>>(n);
    k_scanblk<<<1, 32>>>(SC_B);
    k_scanout<<<SC_B, 256>>>(n);     // offsets + cursors + dinv
    k_fill<<<gb(E, TB), TB>>>(ei, E);

    // --- join, then scale layer-1 t by dinv and gather ---
    cudaStreamWaitEvent(0, evGemm1, 0);
    k_scale<16><<<gb((long long)n * 16, TB), TB>>>(n);
    k_gather<16, 1><<<gb((long long)n * 4, TB), TB>>>(b1, n);

    // --- layer 2: hA -> hB  (16 -> 24) ---
    k_gemm<16, 24, 1, 1><<<gb(n, 128), 128>>>(nullptr, nullptr, W2, n);
    k_gather<24, 2><<<gb((long long)n * 6, TB), TB>>>(b2, n);

    // --- layer 3: hB -> hA  (24 -> 32) ---
    k_gemm<24, 32, 2, 1><<<gb(n, 128), 128>>>(nullptr, nullptr, W3, n);
    k_gather<32, 1><<<gb((long long)n * 8, TB), TB>>>(b3, n);

    // --- start head ---
    k_head<16, 0><<<gb(n, 128), 128>>>(Ws1, bs1, Ws2, bs2, n);
    k_colmax<0><<<256, 256>>>(n);
    k_redmax<<<1, 32>>>();
    k_colsum<0><<<256, 256>>>(n);
    k_redsum<<<1, 32>>>(0);
    k_start<<<gb(n, TB), TB>>>(o_sn, o_sp, n);

    // --- end head (second half of `combined` duplicates rows 0..9) ---
    k_head<24, 1><<<gb(n, 128), 128>>>(We1, be1, We2, be2, n);
    k_colmax<1><<<256, 256>>>(n);
    k_redmax<<<1, 32>>>();
    k_colsum<1><<<256, 256>>>(n);
    k_redsum<<<1, 32>>>(1);
    k_end1<<<gb(n, TB), TB>>>(o_en, o_ep, n);
    k_end2<<<gb(n, TB), TB>>>(o_en, o_ep, n);
}